// round 6
// baseline (speedup 1.0000x reference)
#include <cuda_runtime.h>
#include <cuda_bf16.h>
#include <cstdint>

// Problem constants (fixed by the reference: B=4096, D=512)
#define BHALF 4096
#define NROWS 8192
#define DIM   512

constexpr int TILE  = 128;                       // output tile 128x128
constexpr int KCH   = 128;                       // K chunk (fp8 elements = bytes)
constexpr int NKCH  = DIM / KCH;                 // 4
constexpr int LDSTB = 144;                       // padded smem row stride in BYTES
constexpr int NTILE = NROWS / TILE;              // 64
constexpr int NBLK  = NTILE * (NTILE + 1) / 2;   // 2080 upper-tri tiles
constexpr int MAT_BYTES   = TILE * LDSTB;        // 18432 per matrix
constexpr int STAGE_BYTES = 2 * MAT_BYTES;       // A+B = 36864
constexpr int SMEM_BYTES  = 2 * STAGE_BYTES;     // 73728 (two stages)

// Scratch (no cudaMalloc allowed)
__device__ uint8_t g_zn[(size_t)NROWS * DIM];    // normalized rows, e4m3
__device__ float g_rowsum[NROWS];                // sum_{j!=i} exp(2*dot)
__device__ float g_posdot[BHALF];                // fp32 positive-pair dot

// ---------------------------------------------------------------------------
// helpers
// ---------------------------------------------------------------------------
__device__ __forceinline__ uint32_t smem_u32(const void* p) {
    return (uint32_t)__cvta_generic_to_shared(p);
}
__device__ __forceinline__ void cpasync16(uint32_t s, const void* g) {
    asm volatile("cp.async.cg.shared.global [%0], [%1], 16;\n" :: "r"(s), "l"(g));
}
__device__ __forceinline__ void ldmat_x4(uint32_t& r0, uint32_t& r1, uint32_t& r2, uint32_t& r3,
                                         uint32_t addr) {
    asm volatile("ldmatrix.sync.aligned.m8n8.x4.shared.b16 {%0,%1,%2,%3}, [%4];\n"
                 : "=r"(r0), "=r"(r1), "=r"(r2), "=r"(r3)
                 : "r"(addr));
}
// fp8 e4m3 MMA: m16n8k32, fragment byte-layout identical to m16n8k16.bf16
__device__ __forceinline__ void mma16832(float* c, const uint32_t* a,
                                         uint32_t b0, uint32_t b1) {
    asm volatile(
        "mma.sync.aligned.m16n8k32.row.col.f32.e4m3.e4m3.f32 "
        "{%0,%1,%2,%3}, {%4,%5,%6,%7}, {%8,%9}, {%0,%1,%2,%3};\n"
        : "+f"(c[0]), "+f"(c[1]), "+f"(c[2]), "+f"(c[3])
        : "r"(a[0]), "r"(a[1]), "r"(a[2]), "r"(a[3]), "r"(b0), "r"(b1));
}
__device__ __forceinline__ uint32_t f4_to_e4m3x4(float x, float y, float z, float w) {
    uint16_t lo, hi;
    asm volatile("cvt.rn.satfinite.e4m3x2.f32 %0, %1, %2;\n" : "=h"(lo) : "f"(y), "f"(x));
    asm volatile("cvt.rn.satfinite.e4m3x2.f32 %0, %1, %2;\n" : "=h"(hi) : "f"(w), "f"(z));
    return (uint32_t)lo | ((uint32_t)hi << 16);
}

// ---------------------------------------------------------------------------
// Kernel 1: per-pair normalize (rows p and p+B) -> e4m3, fused fp32
// positive-pair dot. Zeros rowsums and output. grid = BHALF, 128 threads.
// ---------------------------------------------------------------------------
__global__ void __launch_bounds__(128) normalize_kernel(const float* __restrict__ zi,
                                                        const float* __restrict__ zj,
                                                        float* __restrict__ d_out) {
    const int p = blockIdx.x;
    const int t = threadIdx.x;
    float4 vi = ((const float4*)(zi + (size_t)p * DIM))[t];
    float4 vj = ((const float4*)(zj + (size_t)p * DIM))[t];
    float ssi = vi.x * vi.x + vi.y * vi.y + vi.z * vi.z + vi.w * vi.w;
    float ssj = vj.x * vj.x + vj.y * vj.y + vj.z * vj.z + vj.w * vj.w;
    float sij = vi.x * vj.x + vi.y * vj.y + vi.z * vj.z + vi.w * vj.w;
    #pragma unroll
    for (int o = 16; o; o >>= 1) {
        ssi += __shfl_xor_sync(0xffffffffu, ssi, o);
        ssj += __shfl_xor_sync(0xffffffffu, ssj, o);
        sij += __shfl_xor_sync(0xffffffffu, sij, o);
    }
    __shared__ float s0[4], s1[4], s2[4];
    if ((t & 31) == 0) { s0[t >> 5] = ssi; s1[t >> 5] = ssj; s2[t >> 5] = sij; }
    __syncthreads();
    float rni = rsqrtf(s0[0] + s0[1] + s0[2] + s0[3]);
    float rnj = rsqrtf(s1[0] + s1[1] + s1[2] + s1[3]);

    ((uint32_t*)(g_zn + (size_t)p * DIM))[t] =
        f4_to_e4m3x4(vi.x * rni, vi.y * rni, vi.z * rni, vi.w * rni);
    ((uint32_t*)(g_zn + (size_t)(p + BHALF) * DIM))[t] =
        f4_to_e4m3x4(vj.x * rnj, vj.y * rnj, vj.z * rnj, vj.w * rnj);

    if (t == 0) {
        g_posdot[p] = (s2[0] + s2[1] + s2[2] + s2[3]) * rni * rnj;
        g_rowsum[p] = 0.0f;
        g_rowsum[p + BHALF] = 0.0f;
        if (p == 0) d_out[0] = 0.0f;
    }
}

// ---------------------------------------------------------------------------
// Kernel 2: symmetric fp8 mma.sync GEMM + fused exp + row/col sums.
// grid = 2080 upper-triangular 128x128 tiles, 128 threads (4 warps, 64x64,
// warp grid 2M x 2N). cp.async 2-stage K pipeline, double-buffered fragments.
// ---------------------------------------------------------------------------
__global__ void __launch_bounds__(128, 2) gemm_rowsum_kernel() {
    extern __shared__ uint8_t sm[];

    // decode upper-tri tile index
    int id = blockIdx.x, rt = 0, rem = NTILE;
    while (id >= rem) { id -= rem; rem--; rt++; }
    const int ct = rt + id;
    const int rowA0 = rt * TILE, rowB0 = ct * TILE;
    const bool isDiag = (rt == ct);

    const int tid  = threadIdx.x;
    const int warp = tid >> 5, lane = tid & 31;
    const int wm = warp & 1;       // warp row (0..1): 64 rows
    const int wn = warp >> 1;      // warp col (0..1): 64 cols

    float acc[4][8][4];
    #pragma unroll
    for (int i = 0; i < 4; i++)
        #pragma unroll
        for (int j = 0; j < 8; j++)
            #pragma unroll
            for (int k = 0; k < 4; k++) acc[i][j][k] = 0.0f;

    // ---- async chunk loader: A (and B unless diag) 128 rows x 128 B
    auto issue_load = [&](int k0, int st) {
        uint32_t sA = smem_u32(sm) + st * STAGE_BYTES;
        uint32_t sB = sA + MAT_BYTES;
        const uint8_t* gA = g_zn + (size_t)rowA0 * DIM + k0;
        const uint8_t* gB = g_zn + (size_t)rowB0 * DIM + k0;
        #pragma unroll
        for (int i = 0; i < 8; i++) {
            int lin = tid + i * 128;          // 0..1023
            int r   = lin >> 3;
            int c16 = (lin & 7) << 4;         // byte col, 16B chunks
            uint32_t soff = r * LDSTB + c16;
            cpasync16(sA + soff, gA + (size_t)r * DIM + c16);
            if (!isDiag) cpasync16(sB + soff, gB + (size_t)r * DIM + c16);
        }
        asm volatile("cp.async.commit_group;\n" ::: "memory");
    };

    // fragment loaders for one k32 step (byte-layout == bf16 k16 frags)
    auto load_frags = [&](const uint8_t* As, const uint8_t* Bs, int kk,
                          uint32_t a[4][4], uint32_t b[4][4]) {
        #pragma unroll
        for (int mf = 0; mf < 4; mf++) {
            int row = wm * 64 + mf * 16 + (lane & 15);
            int kc  = kk * 32 + (lane >> 4) * 16;       // bytes
            ldmat_x4(a[mf][0], a[mf][1], a[mf][2], a[mf][3],
                     smem_u32(As + row * LDSTB + kc));
        }
        #pragma unroll
        for (int nn = 0; nn < 4; nn++) {
            int grp = lane >> 3;
            int nr  = wn * 64 + nn * 16 + (lane & 7) + ((grp >> 1) << 3);
            int kc  = kk * 32 + ((grp & 1) << 4);       // bytes
            ldmat_x4(b[nn][0], b[nn][1], b[nn][2], b[nn][3],
                     smem_u32(Bs + nr * LDSTB + kc));
        }
    };
    auto do_mmas = [&](uint32_t a[4][4], uint32_t b[4][4]) {
        #pragma unroll
        for (int mf = 0; mf < 4; mf++)
            #pragma unroll
            for (int nn = 0; nn < 4; nn++) {
                mma16832(acc[mf][nn * 2 + 0], a[mf], b[nn][0], b[nn][1]);
                mma16832(acc[mf][nn * 2 + 1], a[mf], b[nn][2], b[nn][3]);
            }
    };

    issue_load(0, 0);
    #pragma unroll 1
    for (int k = 0; k < NKCH; k++) {
        if (k + 1 < NKCH) {
            issue_load((k + 1) * KCH, (k + 1) & 1);
            asm volatile("cp.async.wait_group 1;\n" ::: "memory");
        } else {
            asm volatile("cp.async.wait_group 0;\n" ::: "memory");
        }
        __syncthreads();

        const uint8_t* As = sm + (k & 1) * STAGE_BYTES;
        const uint8_t* Bs = isDiag ? As : (As + MAT_BYTES);
        uint32_t fa[2][4][4], fb[2][4][4];
        load_frags(As, Bs, 0, fa[0], fb[0]);
        #pragma unroll
        for (int kk = 0; kk < 4; kk++) {   // 4 k32 steps per 128-elem chunk
            if (kk < 3) load_frags(As, Bs, kk + 1, fa[(kk + 1) & 1], fb[(kk + 1) & 1]);
            do_mmas(fa[kk & 1], fb[kk & 1]);
        }
        __syncthreads();   // all warps done reading before next load overwrites
    }

    // ---- epilogue: exp(2*dot); keep col>row (full off-diag tiles, strict
    //      upper on diag tiles); accumulate row sums and column sums.
    float rs[4][2];
    #pragma unroll
    for (int mf = 0; mf < 4; mf++) { rs[mf][0] = 0.f; rs[mf][1] = 0.f; }
    float cs[8][2];
    #pragma unroll
    for (int nf = 0; nf < 8; nf++) { cs[nf][0] = 0.f; cs[nf][1] = 0.f; }

    #pragma unroll
    for (int mf = 0; mf < 4; mf++) {
        int ra = rowA0 + wm * 64 + mf * 16 + (lane >> 2);
        int rb = ra + 8;
        #pragma unroll
        for (int nf = 0; nf < 8; nf++) {
            int c0 = rowB0 + wn * 64 + nf * 8 + ((lane & 3) << 1);
            float e0 = __expf(2.0f * acc[mf][nf][0]);
            float e1 = __expf(2.0f * acc[mf][nf][1]);
            float e2 = __expf(2.0f * acc[mf][nf][2]);
            float e3 = __expf(2.0f * acc[mf][nf][3]);
            if (isDiag) {
                if (c0     <= ra) e0 = 0.f;
                if (c0 + 1 <= ra) e1 = 0.f;
                if (c0     <= rb) e2 = 0.f;
                if (c0 + 1 <= rb) e3 = 0.f;
            }
            rs[mf][0] += e0 + e1;
            rs[mf][1] += e2 + e3;
            cs[nf][0] += e0 + e2;
            cs[nf][1] += e1 + e3;
        }
    }

    // row sums: reduce across lane&3 (4 threads share a row)
    #pragma unroll
    for (int mf = 0; mf < 4; mf++) {
        #pragma unroll
        for (int o = 1; o < 4; o <<= 1) {
            rs[mf][0] += __shfl_xor_sync(0xffffffffu, rs[mf][0], o);
            rs[mf][1] += __shfl_xor_sync(0xffffffffu, rs[mf][1], o);
        }
    }
    if ((lane & 3) == 0) {
        int r0 = rowA0 + wm * 64 + (lane >> 2);
        #pragma unroll
        for (int mf = 0; mf < 4; mf++) {
            atomicAdd(&g_rowsum[r0 + mf * 16],     rs[mf][0]);
            atomicAdd(&g_rowsum[r0 + mf * 16 + 8], rs[mf][1]);
        }
    }

    // col sums: reduce across lane>>2 (8 threads share a column group)
    #pragma unroll
    for (int nf = 0; nf < 8; nf++) {
        #pragma unroll
        for (int o = 4; o < 32; o <<= 1) {
            cs[nf][0] += __shfl_xor_sync(0xffffffffu, cs[nf][0], o);
            cs[nf][1] += __shfl_xor_sync(0xffffffffu, cs[nf][1], o);
        }
    }
    if (lane < 4) {
        #pragma unroll
        for (int nf = 0; nf < 8; nf++) {
            int c0 = rowB0 + wn * 64 + nf * 8 + lane * 2;
            atomicAdd(&g_rowsum[c0],     cs[nf][0]);
            atomicAdd(&g_rowsum[c0 + 1], cs[nf][1]);
        }
    }
}

// ---------------------------------------------------------------------------
// Kernel 3: final loss.
// loss = -(1/2B) * sum_p [4*posdot(p) - log(rs_p) - log(rs_{p+B})]
// ---------------------------------------------------------------------------
__global__ void __launch_bounds__(128) loss_kernel(float* __restrict__ d_out) {
    const int p = blockIdx.x * 128 + threadIdx.x;
    float c = 4.0f * g_posdot[p] - logf(g_rowsum[p]) - logf(g_rowsum[p + BHALF]);
    #pragma unroll
    for (int o = 16; o; o >>= 1) c += __shfl_xor_sync(0xffffffffu, c, o);
    __shared__ float ws[4];
    int t = threadIdx.x;
    if ((t & 31) == 0) ws[t >> 5] = c;
    __syncthreads();
    if (t == 0)
        atomicAdd(d_out, (ws[0] + ws[1] + ws[2] + ws[3]) * (-1.0f / (float)NROWS));
}

// ---------------------------------------------------------------------------
extern "C" void kernel_launch(void* const* d_in, const int* in_sizes, int n_in,
                              void* d_out, int out_size) {
    const float* zi = (const float*)d_in[0];
    const float* zj = (const float*)d_in[1];
    float* out = (float*)d_out;

    static bool attr_set = false;
    if (!attr_set) {
        cudaFuncSetAttribute(gemm_rowsum_kernel,
                             cudaFuncAttributeMaxDynamicSharedMemorySize, SMEM_BYTES);
        attr_set = true;
    }

    normalize_kernel<<<BHALF, 128>>>(zi, zj, out);
    gemm_rowsum_kernel<<<NBLK, 128, SMEM_BYTES>>>();
    loss_kernel<<<32, 128>>>(out);
}

// round 7
// speedup vs baseline: 1.7942x; 1.7942x over previous
#include <cuda_runtime.h>
#include <cuda_bf16.h>
#include <cstdint>

// Problem constants (fixed by the reference: B=4096, D=512)
#define BHALF 4096
#define NROWS 8192
#define DIM   512

constexpr int TILE  = 128;                       // output tile 128x128
constexpr int KCH   = 128;                       // K chunk (int8 elements = bytes)
constexpr int NKCH  = DIM / KCH;                 // 4
constexpr int LDSTB = 144;                       // padded smem row stride in BYTES
constexpr int NTILE = NROWS / TILE;              // 64
constexpr int NBLK  = NTILE * (NTILE + 1) / 2;   // 2080 upper-tri tiles
constexpr int MAT_BYTES   = TILE * LDSTB;        // 18432 per matrix
constexpr int STAGE_BYTES = 2 * MAT_BYTES;       // A+B = 36864
constexpr int SMEM_BYTES  = 2 * STAGE_BYTES;     // 73728 (two stages)

constexpr float QSCALE   = 400.0f;               // int8 quantization scale
constexpr float DEQ2     = 2.0f / (QSCALE * QSCALE);   // folds the 2/temp... (2*dot)

// Scratch (no cudaMalloc allowed)
__device__ uint8_t g_zn[(size_t)NROWS * DIM];    // normalized rows, s8 (as bytes)
__device__ float g_rowsum[NROWS];                // sum_{j!=i} exp(2*dot)
__device__ float g_posdot[BHALF];                // fp32 positive-pair dot

// ---------------------------------------------------------------------------
// helpers
// ---------------------------------------------------------------------------
__device__ __forceinline__ uint32_t smem_u32(const void* p) {
    return (uint32_t)__cvta_generic_to_shared(p);
}
__device__ __forceinline__ void cpasync16(uint32_t s, const void* g) {
    asm volatile("cp.async.cg.shared.global [%0], [%1], 16;\n" :: "r"(s), "l"(g));
}
__device__ __forceinline__ void ldmat_x4(uint32_t& r0, uint32_t& r1, uint32_t& r2, uint32_t& r3,
                                         uint32_t addr) {
    asm volatile("ldmatrix.sync.aligned.m8n8.x4.shared.b16 {%0,%1,%2,%3}, [%4];\n"
                 : "=r"(r0), "=r"(r1), "=r"(r2), "=r"(r3)
                 : "r"(addr));
}
// int8 IMMA: m16n8k32, s32 accumulators; fragment layout identical to fp8 k32
__device__ __forceinline__ void mma16832(int* c, const uint32_t* a,
                                         uint32_t b0, uint32_t b1) {
    asm volatile(
        "mma.sync.aligned.m16n8k32.row.col.s32.s8.s8.s32 "
        "{%0,%1,%2,%3}, {%4,%5,%6,%7}, {%8,%9}, {%0,%1,%2,%3};\n"
        : "+r"(c[0]), "+r"(c[1]), "+r"(c[2]), "+r"(c[3])
        : "r"(a[0]), "r"(a[1]), "r"(a[2]), "r"(a[3]), "r"(b0), "r"(b1));
}
__device__ __forceinline__ int q8(float v) {
    int q = __float2int_rn(v * QSCALE);
    return max(-127, min(127, q));
}
__device__ __forceinline__ uint32_t pack_s8x4(float x, float y, float z, float w) {
    return (uint32_t)(q8(x) & 0xFF) | ((uint32_t)(q8(y) & 0xFF) << 8) |
           ((uint32_t)(q8(z) & 0xFF) << 16) | ((uint32_t)(q8(w) & 0xFF) << 24);
}

// ---------------------------------------------------------------------------
// Kernel 1: per-pair normalize (rows p and p+B) -> s8, fused fp32
// positive-pair dot. Zeros rowsums and output. grid = BHALF, 128 threads.
// ---------------------------------------------------------------------------
__global__ void __launch_bounds__(128) normalize_kernel(const float* __restrict__ zi,
                                                        const float* __restrict__ zj,
                                                        float* __restrict__ d_out) {
    const int p = blockIdx.x;
    const int t = threadIdx.x;
    float4 vi = ((const float4*)(zi + (size_t)p * DIM))[t];
    float4 vj = ((const float4*)(zj + (size_t)p * DIM))[t];
    float ssi = vi.x * vi.x + vi.y * vi.y + vi.z * vi.z + vi.w * vi.w;
    float ssj = vj.x * vj.x + vj.y * vj.y + vj.z * vj.z + vj.w * vj.w;
    float sij = vi.x * vj.x + vi.y * vj.y + vi.z * vj.z + vi.w * vj.w;
    #pragma unroll
    for (int o = 16; o; o >>= 1) {
        ssi += __shfl_xor_sync(0xffffffffu, ssi, o);
        ssj += __shfl_xor_sync(0xffffffffu, ssj, o);
        sij += __shfl_xor_sync(0xffffffffu, sij, o);
    }
    __shared__ float s0[4], s1[4], s2[4];
    if ((t & 31) == 0) { s0[t >> 5] = ssi; s1[t >> 5] = ssj; s2[t >> 5] = sij; }
    __syncthreads();
    float rni = rsqrtf(s0[0] + s0[1] + s0[2] + s0[3]);
    float rnj = rsqrtf(s1[0] + s1[1] + s1[2] + s1[3]);

    ((uint32_t*)(g_zn + (size_t)p * DIM))[t] =
        pack_s8x4(vi.x * rni, vi.y * rni, vi.z * rni, vi.w * rni);
    ((uint32_t*)(g_zn + (size_t)(p + BHALF) * DIM))[t] =
        pack_s8x4(vj.x * rnj, vj.y * rnj, vj.z * rnj, vj.w * rnj);

    if (t == 0) {
        g_posdot[p] = (s2[0] + s2[1] + s2[2] + s2[3]) * rni * rnj;
        g_rowsum[p] = 0.0f;
        g_rowsum[p + BHALF] = 0.0f;
        if (p == 0) d_out[0] = 0.0f;
    }
}

// ---------------------------------------------------------------------------
// Kernel 2: symmetric int8 mma.sync GEMM + fused exp + row/col sums.
// grid = 2080 upper-triangular 128x128 tiles, 128 threads (4 warps, 64x64,
// warp grid 2M x 2N). cp.async 2-stage K pipeline, double-buffered fragments.
// ---------------------------------------------------------------------------
__global__ void __launch_bounds__(128, 2) gemm_rowsum_kernel() {
    extern __shared__ uint8_t sm[];

    // decode upper-tri tile index
    int id = blockIdx.x, rt = 0, rem = NTILE;
    while (id >= rem) { id -= rem; rem--; rt++; }
    const int ct = rt + id;
    const int rowA0 = rt * TILE, rowB0 = ct * TILE;
    const bool isDiag = (rt == ct);

    const int tid  = threadIdx.x;
    const int warp = tid >> 5, lane = tid & 31;
    const int wm = warp & 1;       // warp row (0..1): 64 rows
    const int wn = warp >> 1;      // warp col (0..1): 64 cols

    int acc[4][8][4];
    #pragma unroll
    for (int i = 0; i < 4; i++)
        #pragma unroll
        for (int j = 0; j < 8; j++)
            #pragma unroll
            for (int k = 0; k < 4; k++) acc[i][j][k] = 0;

    // ---- async chunk loader: A (and B unless diag) 128 rows x 128 B
    auto issue_load = [&](int k0, int st) {
        uint32_t sA = smem_u32(sm) + st * STAGE_BYTES;
        uint32_t sB = sA + MAT_BYTES;
        const uint8_t* gA = g_zn + (size_t)rowA0 * DIM + k0;
        const uint8_t* gB = g_zn + (size_t)rowB0 * DIM + k0;
        #pragma unroll
        for (int i = 0; i < 8; i++) {
            int lin = tid + i * 128;          // 0..1023
            int r   = lin >> 3;
            int c16 = (lin & 7) << 4;         // byte col, 16B chunks
            uint32_t soff = r * LDSTB + c16;
            cpasync16(sA + soff, gA + (size_t)r * DIM + c16);
            if (!isDiag) cpasync16(sB + soff, gB + (size_t)r * DIM + c16);
        }
        asm volatile("cp.async.commit_group;\n" ::: "memory");
    };

    // fragment loaders for one k32 step
    auto load_frags = [&](const uint8_t* As, const uint8_t* Bs, int kk,
                          uint32_t a[4][4], uint32_t b[4][4]) {
        #pragma unroll
        for (int mf = 0; mf < 4; mf++) {
            int row = wm * 64 + mf * 16 + (lane & 15);
            int kc  = kk * 32 + (lane >> 4) * 16;       // bytes
            ldmat_x4(a[mf][0], a[mf][1], a[mf][2], a[mf][3],
                     smem_u32(As + row * LDSTB + kc));
        }
        #pragma unroll
        for (int nn = 0; nn < 4; nn++) {
            int grp = lane >> 3;
            int nr  = wn * 64 + nn * 16 + (lane & 7) + ((grp >> 1) << 3);
            int kc  = kk * 32 + ((grp & 1) << 4);       // bytes
            ldmat_x4(b[nn][0], b[nn][1], b[nn][2], b[nn][3],
                     smem_u32(Bs + nr * LDSTB + kc));
        }
    };
    auto do_mmas = [&](uint32_t a[4][4], uint32_t b[4][4]) {
        #pragma unroll
        for (int mf = 0; mf < 4; mf++)
            #pragma unroll
            for (int nn = 0; nn < 4; nn++) {
                mma16832(acc[mf][nn * 2 + 0], a[mf], b[nn][0], b[nn][1]);
                mma16832(acc[mf][nn * 2 + 1], a[mf], b[nn][2], b[nn][3]);
            }
    };

    issue_load(0, 0);
    #pragma unroll 1
    for (int k = 0; k < NKCH; k++) {
        if (k + 1 < NKCH) {
            issue_load((k + 1) * KCH, (k + 1) & 1);
            asm volatile("cp.async.wait_group 1;\n" ::: "memory");
        } else {
            asm volatile("cp.async.wait_group 0;\n" ::: "memory");
        }
        __syncthreads();

        const uint8_t* As = sm + (k & 1) * STAGE_BYTES;
        const uint8_t* Bs = isDiag ? As : (As + MAT_BYTES);
        uint32_t fa[2][4][4], fb[2][4][4];
        load_frags(As, Bs, 0, fa[0], fb[0]);
        #pragma unroll
        for (int kk = 0; kk < 4; kk++) {   // 4 k32 steps per 128-elem chunk
            if (kk < 3) load_frags(As, Bs, kk + 1, fa[(kk + 1) & 1], fb[(kk + 1) & 1]);
            do_mmas(fa[kk & 1], fb[kk & 1]);
        }
        __syncthreads();   // all warps done reading before next load overwrites
    }

    // ---- epilogue: exp(2*dot) with dot = acc/QSCALE^2; keep col>row.
    float rs[4][2];
    #pragma unroll
    for (int mf = 0; mf < 4; mf++) { rs[mf][0] = 0.f; rs[mf][1] = 0.f; }
    float cs[8][2];
    #pragma unroll
    for (int nf = 0; nf < 8; nf++) { cs[nf][0] = 0.f; cs[nf][1] = 0.f; }

    #pragma unroll
    for (int mf = 0; mf < 4; mf++) {
        int ra = rowA0 + wm * 64 + mf * 16 + (lane >> 2);
        int rb = ra + 8;
        #pragma unroll
        for (int nf = 0; nf < 8; nf++) {
            int c0 = rowB0 + wn * 64 + nf * 8 + ((lane & 3) << 1);
            float e0 = __expf(DEQ2 * (float)acc[mf][nf][0]);
            float e1 = __expf(DEQ2 * (float)acc[mf][nf][1]);
            float e2 = __expf(DEQ2 * (float)acc[mf][nf][2]);
            float e3 = __expf(DEQ2 * (float)acc[mf][nf][3]);
            if (isDiag) {
                if (c0     <= ra) e0 = 0.f;
                if (c0 + 1 <= ra) e1 = 0.f;
                if (c0     <= rb) e2 = 0.f;
                if (c0 + 1 <= rb) e3 = 0.f;
            }
            rs[mf][0] += e0 + e1;
            rs[mf][1] += e2 + e3;
            cs[nf][0] += e0 + e2;
            cs[nf][1] += e1 + e3;
        }
    }

    // row sums: reduce across lane&3 (4 threads share a row)
    #pragma unroll
    for (int mf = 0; mf < 4; mf++) {
        #pragma unroll
        for (int o = 1; o < 4; o <<= 1) {
            rs[mf][0] += __shfl_xor_sync(0xffffffffu, rs[mf][0], o);
            rs[mf][1] += __shfl_xor_sync(0xffffffffu, rs[mf][1], o);
        }
    }
    if ((lane & 3) == 0) {
        int r0 = rowA0 + wm * 64 + (lane >> 2);
        #pragma unroll
        for (int mf = 0; mf < 4; mf++) {
            atomicAdd(&g_rowsum[r0 + mf * 16],     rs[mf][0]);
            atomicAdd(&g_rowsum[r0 + mf * 16 + 8], rs[mf][1]);
        }
    }

    // col sums: reduce across lane>>2 (8 threads share a column group)
    #pragma unroll
    for (int nf = 0; nf < 8; nf++) {
        #pragma unroll
        for (int o = 4; o < 32; o <<= 1) {
            cs[nf][0] += __shfl_xor_sync(0xffffffffu, cs[nf][0], o);
            cs[nf][1] += __shfl_xor_sync(0xffffffffu, cs[nf][1], o);
        }
    }
    if (lane < 4) {
        #pragma unroll
        for (int nf = 0; nf < 8; nf++) {
            int c0 = rowB0 + wn * 64 + nf * 8 + lane * 2;
            atomicAdd(&g_rowsum[c0],     cs[nf][0]);
            atomicAdd(&g_rowsum[c0 + 1], cs[nf][1]);
        }
    }
}

// ---------------------------------------------------------------------------
// Kernel 3: final loss.
// loss = -(1/2B) * sum_p [4*posdot(p) - log(rs_p) - log(rs_{p+B})]
// ---------------------------------------------------------------------------
__global__ void __launch_bounds__(128) loss_kernel(float* __restrict__ d_out) {
    const int p = blockIdx.x * 128 + threadIdx.x;
    float c = 4.0f * g_posdot[p] - logf(g_rowsum[p]) - logf(g_rowsum[p + BHALF]);
    #pragma unroll
    for (int o = 16; o; o >>= 1) c += __shfl_xor_sync(0xffffffffu, c, o);
    __shared__ float ws[4];
    int t = threadIdx.x;
    if ((t & 31) == 0) ws[t >> 5] = c;
    __syncthreads();
    if (t == 0)
        atomicAdd(d_out, (ws[0] + ws[1] + ws[2] + ws[3]) * (-1.0f / (float)NROWS));
}

// ---------------------------------------------------------------------------
extern "C" void kernel_launch(void* const* d_in, const int* in_sizes, int n_in,
                              void* d_out, int out_size) {
    const float* zi = (const float*)d_in[0];
    const float* zj = (const float*)d_in[1];
    float* out = (float*)d_out;

    static bool attr_set = false;
    if (!attr_set) {
        cudaFuncSetAttribute(gemm_rowsum_kernel,
                             cudaFuncAttributeMaxDynamicSharedMemorySize, SMEM_BYTES);
        attr_set = true;
    }

    normalize_kernel<<<BHALF, 128>>>(zi, zj, out);
    gemm_rowsum_kernel<<<NBLK, 128, SMEM_BYTES>>>();
    loss_kernel<<<32, 128>>>(out);
}